// round 1
// baseline (speedup 1.0000x reference)
#include <cuda_runtime.h>
#include <cuda_bf16.h>
#include <math.h>

#define B_  2
#define N_  2048
#define C_  1024
#define H_  16
#define DH  64

// Scratch (device globals: allocation-free per harness rules)
__device__ float g_q[B_*H_*N_*DH];
__device__ float g_k[B_*H_*N_*DH];
__device__ float g_v[B_*H_*N_*DH];
__device__ float g_att[B_*N_*C_];

// ---------------------------------------------------------------------------
// QKV GEMM: C[m][j] = sum_k x[m][k] * qkv_w[j][k]
// M=4096, N=3072, K=1024. Tile 64x64x16, 256 threads, 4x4 microtile.
// Epilogue scatters into g_q/g_k/g_v in [B,H,N,DH] layout.
// ---------------------------------------------------------------------------
__global__ __launch_bounds__(256) void qkv_gemm_kernel(
    const float* __restrict__ x, const float* __restrict__ w)
{
    __shared__ __align__(16) float As[16][64];  // As[k][m]
    __shared__ __align__(16) float Ws[16][64];  // Ws[k][j]

    const int tid = threadIdx.x;
    const int tx = tid & 15;
    const int ty = tid >> 4;
    const int m0 = blockIdx.y * 64;
    const int j0 = blockIdx.x * 64;

    const int lr = tid >> 2;      // 0..63  row within tile
    const int lk = (tid & 3) * 4; // 0,4,8,12 k within tile

    float acc[4][4];
    #pragma unroll
    for (int u = 0; u < 4; u++)
        #pragma unroll
        for (int v = 0; v < 4; v++) acc[u][v] = 0.f;

    for (int k0 = 0; k0 < C_; k0 += 16) {
        float4 av = *reinterpret_cast<const float4*>(&x[(m0 + lr) * C_ + k0 + lk]);
        float4 wv = *reinterpret_cast<const float4*>(&w[(j0 + lr) * C_ + k0 + lk]);
        As[lk + 0][lr] = av.x; As[lk + 1][lr] = av.y;
        As[lk + 2][lr] = av.z; As[lk + 3][lr] = av.w;
        Ws[lk + 0][lr] = wv.x; Ws[lk + 1][lr] = wv.y;
        Ws[lk + 2][lr] = wv.z; Ws[lk + 3][lr] = wv.w;
        __syncthreads();

        #pragma unroll
        for (int k = 0; k < 16; k++) {
            float4 a = *reinterpret_cast<const float4*>(&As[k][ty * 4]);
            float4 b = *reinterpret_cast<const float4*>(&Ws[k][tx * 4]);
            acc[0][0] += a.x * b.x; acc[0][1] += a.x * b.y; acc[0][2] += a.x * b.z; acc[0][3] += a.x * b.w;
            acc[1][0] += a.y * b.x; acc[1][1] += a.y * b.y; acc[1][2] += a.y * b.z; acc[1][3] += a.y * b.w;
            acc[2][0] += a.z * b.x; acc[2][1] += a.z * b.y; acc[2][2] += a.z * b.z; acc[2][3] += a.z * b.w;
            acc[3][0] += a.w * b.x; acc[3][1] += a.w * b.y; acc[3][2] += a.w * b.z; acc[3][3] += a.w * b.w;
        }
        __syncthreads();
    }

    // Epilogue: tile spans exactly one (which, head); d = tx*4..tx*4+3 contiguous
    const int j = j0 + tx * 4;
    const int which = j >> 10;
    const int h = (j >> 6) & (H_ - 1);
    const int d = j & (DH - 1);
    float* dst = (which == 0) ? g_q : (which == 1) ? g_k : g_v;

    #pragma unroll
    for (int u = 0; u < 4; u++) {
        const int m = m0 + ty * 4 + u;
        const int b = m >> 11;
        const int n = m & (N_ - 1);
        float4 o = make_float4(acc[u][0], acc[u][1], acc[u][2], acc[u][3]);
        *reinterpret_cast<float4*>(&dst[(((size_t)b * H_ + h) * N_ + n) * DH + d]) = o;
    }
}

// ---------------------------------------------------------------------------
// RoPE 2D applied in-place to g_q and g_k.
// One thread per (b,h,n, pair). 32 pairs per row of 64 dims.
// pair p: halfsel = p/16 (y vs x half), i = p%16 (freq index)
// d1 = halfsel*32 + i, d2 = d1+16, angle = pos[b][n][halfsel] * 100^(-i/16)
// ---------------------------------------------------------------------------
__global__ __launch_bounds__(256) void rope_kernel(const int* __restrict__ pos)
{
    const int t = blockIdx.x * blockDim.x + threadIdx.x;
    const int total = B_ * H_ * N_ * 32;
    if (t >= total) return;

    const int p = t & 31;
    const int row = t >> 5;           // (b*H + h)*N + n
    const int n = row & (N_ - 1);
    const int bh = row >> 11;
    const int b = bh >> 4;

    const int halfsel = p >> 4;
    const int i = p & 15;
    const int d1 = halfsel * 32 + i;
    const int d2 = d1 + 16;

    const float posv = (float)pos[((size_t)b * N_ + n) * 2 + halfsel];
    const float inv_freq = powf(100.0f, -(float)i / 16.0f);
    const float ang = posv * inv_freq;
    float c, s;
    __sincosf(ang, &s, &c);
    // use accurate versions to stay tight to reference:
    s = sinf(ang);
    c = cosf(ang);

    const size_t base = (size_t)row * DH;
    float q1 = g_q[base + d1], q2 = g_q[base + d2];
    g_q[base + d1] = q1 * c - q2 * s;
    g_q[base + d2] = q1 * s + q2 * c;
    float k1 = g_k[base + d1], k2 = g_k[base + d2];
    g_k[base + d1] = k1 * c - k2 * s;
    g_k[base + d2] = k1 * s + k2 * c;
}

// ---------------------------------------------------------------------------
// Flash attention: one CTA per (b, h, 64-row q tile). 256 threads.
// Smem: Qs[d][i] stride 68, Ks[d][j] stride 68, Vs[j][d] stride 64,
//       Ps[i][j] stride 65.
// ---------------------------------------------------------------------------
#define QS_STR 68
#define PS_STR 65
#define SMEM_FLOATS (64*QS_STR + 64*QS_STR + 64*64 + 64*PS_STR)

__global__ __launch_bounds__(256) void attn_kernel()
{
    extern __shared__ __align__(16) float sm[];
    float* Qs = sm;                       // [64][68]  (d-major)
    float* Ks = sm + 64 * QS_STR;         // [64][68]  (d-major)
    float* Vs = sm + 2 * 64 * QS_STR;     // [64][64]  (j-major)
    float* Ps = sm + 2 * 64 * QS_STR + 64 * 64; // [64][65]

    const int tid = threadIdx.x;
    const int tx = tid & 15;
    const int ty = tid >> 4;
    const int q0 = blockIdx.x * 64;
    const int h = blockIdx.y;
    const int b = blockIdx.z;

    const float* qptr = g_q + ((size_t)b * H_ + h) * N_ * DH;
    const float* kptr = g_k + ((size_t)b * H_ + h) * N_ * DH;
    const float* vptr = g_v + ((size_t)b * H_ + h) * N_ * DH;

    const float scale = 0.125f; // 64^-0.5

    // Load Q tile transposed: Qs[d][i]
    for (int i4 = tid; i4 < 1024; i4 += 256) {
        const int r = i4 >> 4;
        const int d4 = (i4 & 15) * 4;
        float4 qv = *reinterpret_cast<const float4*>(&qptr[(size_t)(q0 + r) * DH + d4]);
        Qs[(d4 + 0) * QS_STR + r] = qv.x;
        Qs[(d4 + 1) * QS_STR + r] = qv.y;
        Qs[(d4 + 2) * QS_STR + r] = qv.z;
        Qs[(d4 + 3) * QS_STR + r] = qv.w;
    }

    float m[4], l[4], acc[4][4];
    #pragma unroll
    for (int u = 0; u < 4; u++) {
        m[u] = -1e30f;
        l[u] = 0.f;
        #pragma unroll
        for (int v = 0; v < 4; v++) acc[u][v] = 0.f;
    }

    for (int kt = 0; kt < N_ / 64; kt++) {
        __syncthreads(); // protect Ks/Vs from previous iteration readers
        const int n0 = kt * 64;
        for (int i4 = tid; i4 < 1024; i4 += 256) {
            const int r = i4 >> 4;
            const int d4 = (i4 & 15) * 4;
            float4 kv = *reinterpret_cast<const float4*>(&kptr[(size_t)(n0 + r) * DH + d4]);
            Ks[(d4 + 0) * QS_STR + r] = kv.x;
            Ks[(d4 + 1) * QS_STR + r] = kv.y;
            Ks[(d4 + 2) * QS_STR + r] = kv.z;
            Ks[(d4 + 3) * QS_STR + r] = kv.w;
            float4 vv = *reinterpret_cast<const float4*>(&vptr[(size_t)(n0 + r) * DH + d4]);
            *reinterpret_cast<float4*>(&Vs[r * 64 + d4]) = vv;
        }
        __syncthreads();

        // S = Q K^T  (4x4 microtile per thread; rows ty*4+u, cols tx*4+v)
        float s[4][4];
        #pragma unroll
        for (int u = 0; u < 4; u++)
            #pragma unroll
            for (int v = 0; v < 4; v++) s[u][v] = 0.f;

        #pragma unroll 8
        for (int d = 0; d < 64; d++) {
            float4 a = *reinterpret_cast<const float4*>(&Qs[d * QS_STR + ty * 4]);
            float4 bb = *reinterpret_cast<const float4*>(&Ks[d * QS_STR + tx * 4]);
            s[0][0] += a.x * bb.x; s[0][1] += a.x * bb.y; s[0][2] += a.x * bb.z; s[0][3] += a.x * bb.w;
            s[1][0] += a.y * bb.x; s[1][1] += a.y * bb.y; s[1][2] += a.y * bb.z; s[1][3] += a.y * bb.w;
            s[2][0] += a.z * bb.x; s[2][1] += a.z * bb.y; s[2][2] += a.z * bb.z; s[2][3] += a.z * bb.w;
            s[3][0] += a.w * bb.x; s[3][1] += a.w * bb.y; s[3][2] += a.w * bb.z; s[3][3] += a.w * bb.w;
        }

        // Online softmax update
        #pragma unroll
        for (int u = 0; u < 4; u++) {
            float rmax = -1e30f;
            #pragma unroll
            for (int v = 0; v < 4; v++) {
                s[u][v] *= scale;
                rmax = fmaxf(rmax, s[u][v]);
            }
            #pragma unroll
            for (int off = 1; off < 16; off <<= 1)
                rmax = fmaxf(rmax, __shfl_xor_sync(0xffffffffu, rmax, off));

            const float newm = fmaxf(m[u], rmax);
            const float corr = expf(m[u] - newm);
            float rsum = 0.f;
            #pragma unroll
            for (int v = 0; v < 4; v++) {
                s[u][v] = expf(s[u][v] - newm);
                rsum += s[u][v];
            }
            #pragma unroll
            for (int off = 1; off < 16; off <<= 1)
                rsum += __shfl_xor_sync(0xffffffffu, rsum, off);

            l[u] = l[u] * corr + rsum;
            m[u] = newm;
            #pragma unroll
            for (int v = 0; v < 4; v++) {
                acc[u][v] *= corr;
                Ps[(ty * 4 + u) * PS_STR + tx * 4 + v] = s[u][v];
            }
        }
        __syncthreads();

        // O += P @ V  (rows ty*4+u, dims tx*4+v)
        #pragma unroll 4
        for (int j = 0; j < 64; j++) {
            float4 v4 = *reinterpret_cast<const float4*>(&Vs[j * 64 + tx * 4]);
            float p0 = Ps[(ty * 4 + 0) * PS_STR + j];
            float p1 = Ps[(ty * 4 + 1) * PS_STR + j];
            float p2 = Ps[(ty * 4 + 2) * PS_STR + j];
            float p3 = Ps[(ty * 4 + 3) * PS_STR + j];
            acc[0][0] += p0 * v4.x; acc[0][1] += p0 * v4.y; acc[0][2] += p0 * v4.z; acc[0][3] += p0 * v4.w;
            acc[1][0] += p1 * v4.x; acc[1][1] += p1 * v4.y; acc[1][2] += p1 * v4.z; acc[1][3] += p1 * v4.w;
            acc[2][0] += p2 * v4.x; acc[2][1] += p2 * v4.y; acc[2][2] += p2 * v4.z; acc[2][3] += p2 * v4.w;
            acc[3][0] += p3 * v4.x; acc[3][1] += p3 * v4.y; acc[3][2] += p3 * v4.z; acc[3][3] += p3 * v4.w;
        }
    }

    // Write normalized output to g_att in [B, N, H*DH] layout
    #pragma unroll
    for (int u = 0; u < 4; u++) {
        const float inv_l = 1.0f / l[u];
        const int n = q0 + ty * 4 + u;
        float4 o = make_float4(acc[u][0] * inv_l, acc[u][1] * inv_l,
                               acc[u][2] * inv_l, acc[u][3] * inv_l);
        *reinterpret_cast<float4*>(&g_att[((size_t)b * N_ + n) * C_ + h * DH + tx * 4]) = o;
    }
}

// ---------------------------------------------------------------------------
// Output projection: out[m][j] = sum_k g_att[m][k] * proj_w[j][k] + proj_b[j]
// M=4096, N=1024, K=1024
// ---------------------------------------------------------------------------
__global__ __launch_bounds__(256) void proj_gemm_kernel(
    const float* __restrict__ w, const float* __restrict__ bias,
    float* __restrict__ out)
{
    __shared__ __align__(16) float As[16][64];
    __shared__ __align__(16) float Ws[16][64];

    const int tid = threadIdx.x;
    const int tx = tid & 15;
    const int ty = tid >> 4;
    const int m0 = blockIdx.y * 64;
    const int j0 = blockIdx.x * 64;

    const int lr = tid >> 2;
    const int lk = (tid & 3) * 4;

    float acc[4][4];
    #pragma unroll
    for (int u = 0; u < 4; u++)
        #pragma unroll
        for (int v = 0; v < 4; v++) acc[u][v] = 0.f;

    for (int k0 = 0; k0 < C_; k0 += 16) {
        float4 av = *reinterpret_cast<const float4*>(&g_att[(size_t)(m0 + lr) * C_ + k0 + lk]);
        float4 wv = *reinterpret_cast<const float4*>(&w[(size_t)(j0 + lr) * C_ + k0 + lk]);
        As[lk + 0][lr] = av.x; As[lk + 1][lr] = av.y;
        As[lk + 2][lr] = av.z; As[lk + 3][lr] = av.w;
        Ws[lk + 0][lr] = wv.x; Ws[lk + 1][lr] = wv.y;
        Ws[lk + 2][lr] = wv.z; Ws[lk + 3][lr] = wv.w;
        __syncthreads();

        #pragma unroll
        for (int k = 0; k < 16; k++) {
            float4 a = *reinterpret_cast<const float4*>(&As[k][ty * 4]);
            float4 b = *reinterpret_cast<const float4*>(&Ws[k][tx * 4]);
            acc[0][0] += a.x * b.x; acc[0][1] += a.x * b.y; acc[0][2] += a.x * b.z; acc[0][3] += a.x * b.w;
            acc[1][0] += a.y * b.x; acc[1][1] += a.y * b.y; acc[1][2] += a.y * b.z; acc[1][3] += a.y * b.w;
            acc[2][0] += a.z * b.x; acc[2][1] += a.z * b.y; acc[2][2] += a.z * b.z; acc[2][3] += a.z * b.w;
            acc[3][0] += a.w * b.x; acc[3][1] += a.w * b.y; acc[3][2] += a.w * b.z; acc[3][3] += a.w * b.w;
        }
        __syncthreads();
    }

    const int j = j0 + tx * 4;
    float4 bv = *reinterpret_cast<const float4*>(&bias[j]);
    #pragma unroll
    for (int u = 0; u < 4; u++) {
        const int mm = m0 + ty * 4 + u;
        float4 o = make_float4(acc[u][0] + bv.x, acc[u][1] + bv.y,
                               acc[u][2] + bv.z, acc[u][3] + bv.w);
        *reinterpret_cast<float4*>(&out[(size_t)mm * C_ + j]) = o;
    }
}

// ---------------------------------------------------------------------------
extern "C" void kernel_launch(void* const* d_in, const int* in_sizes, int n_in,
                              void* d_out, int out_size)
{
    const float* x      = (const float*)d_in[0];
    const int*   pos    = (const int*)  d_in[1];
    const float* qkv_w  = (const float*)d_in[2];
    const float* proj_w = (const float*)d_in[3];
    const float* proj_b = (const float*)d_in[4];
    float* out = (float*)d_out;

    const int attn_smem = SMEM_FLOATS * (int)sizeof(float); // 67840 B
    cudaFuncSetAttribute(attn_kernel,
                         cudaFuncAttributeMaxDynamicSharedMemorySize, attn_smem);

    // 1) QKV projection + scatter to [B,H,N,DH]
    {
        dim3 grid(3 * C_ / 64, (B_ * N_) / 64); // (48, 64)
        qkv_gemm_kernel<<<grid, 256>>>(x, qkv_w);
    }
    // 2) RoPE on q and k
    {
        const int total = B_ * H_ * N_ * 32;
        rope_kernel<<<(total + 255) / 256, 256>>>(pos);
    }
    // 3) Attention
    {
        dim3 grid(N_ / 64, H_, B_); // (32, 16, 2)
        attn_kernel<<<grid, 256, attn_smem>>>();
    }
    // 4) Output projection + bias
    {
        dim3 grid(C_ / 64, (B_ * N_) / 64); // (16, 64)
        proj_gemm_kernel<<<grid, 256>>>(proj_w, proj_b, out);
    }
}

// round 2
// speedup vs baseline: 1.1878x; 1.1878x over previous
#include <cuda_runtime.h>
#include <cuda_bf16.h>
#include <math.h>

#define B_  2
#define N_  2048
#define C_  1024
#define H_  16
#define DH  64

// Scratch (device globals: allocation-free per harness rules)
__device__ float g_q[B_*H_*N_*DH];
__device__ float g_k[B_*H_*N_*DH];
__device__ float g_v[B_*H_*N_*DH];
__device__ float g_att[B_*N_*C_];

// ---------------------------------------------------------------------------
// QKV GEMM: out[m][j] = sum_k x[m][k] * qkv_w[j][k]
// M=4096, N=3072, K=1024. Tile 128x128x16, 256 threads, 8x8 microtile.
// Epilogue scatters into g_q/g_k/g_v in [B,H,N,DH] layout.
// ---------------------------------------------------------------------------
__global__ __launch_bounds__(256, 2) void qkv_gemm_kernel(
    const float* __restrict__ x, const float* __restrict__ w)
{
    __shared__ __align__(16) float As[16][128];  // As[k][m]
    __shared__ __align__(16) float Ws[16][128];  // Ws[k][j]

    const int tid = threadIdx.x;
    const int tx = tid & 15;
    const int ty = tid >> 4;
    const int m0 = blockIdx.y * 128;
    const int j0 = blockIdx.x * 128;

    const int lr = tid >> 1;       // 0..127 row within tile
    const int lk = (tid & 1) * 8;  // 0 or 8

    float acc[8][8];
    #pragma unroll
    for (int u = 0; u < 8; u++)
        #pragma unroll
        for (int v = 0; v < 8; v++) acc[u][v] = 0.f;

    for (int k0 = 0; k0 < C_; k0 += 16) {
        float4 a0 = *reinterpret_cast<const float4*>(&x[(size_t)(m0 + lr) * C_ + k0 + lk]);
        float4 a1 = *reinterpret_cast<const float4*>(&x[(size_t)(m0 + lr) * C_ + k0 + lk + 4]);
        float4 b0 = *reinterpret_cast<const float4*>(&w[(size_t)(j0 + lr) * C_ + k0 + lk]);
        float4 b1 = *reinterpret_cast<const float4*>(&w[(size_t)(j0 + lr) * C_ + k0 + lk + 4]);
        As[lk + 0][lr] = a0.x; As[lk + 1][lr] = a0.y; As[lk + 2][lr] = a0.z; As[lk + 3][lr] = a0.w;
        As[lk + 4][lr] = a1.x; As[lk + 5][lr] = a1.y; As[lk + 6][lr] = a1.z; As[lk + 7][lr] = a1.w;
        Ws[lk + 0][lr] = b0.x; Ws[lk + 1][lr] = b0.y; Ws[lk + 2][lr] = b0.z; Ws[lk + 3][lr] = b0.w;
        Ws[lk + 4][lr] = b1.x; Ws[lk + 5][lr] = b1.y; Ws[lk + 6][lr] = b1.z; Ws[lk + 7][lr] = b1.w;
        __syncthreads();

        #pragma unroll
        for (int k = 0; k < 16; k++) {
            float a[8], b[8];
            *reinterpret_cast<float4*>(&a[0]) = *reinterpret_cast<const float4*>(&As[k][ty * 8]);
            *reinterpret_cast<float4*>(&a[4]) = *reinterpret_cast<const float4*>(&As[k][ty * 8 + 4]);
            *reinterpret_cast<float4*>(&b[0]) = *reinterpret_cast<const float4*>(&Ws[k][tx * 8]);
            *reinterpret_cast<float4*>(&b[4]) = *reinterpret_cast<const float4*>(&Ws[k][tx * 8 + 4]);
            #pragma unroll
            for (int u = 0; u < 8; u++)
                #pragma unroll
                for (int v = 0; v < 8; v++)
                    acc[u][v] += a[u] * b[v];
        }
        __syncthreads();
    }

    // Epilogue: j block = j0 + tx*8 .. +7, all within one (which, head)
    const int j = j0 + tx * 8;
    const int which = j >> 10;
    const int h = (j >> 6) & (H_ - 1);
    const int d = j & (DH - 1);
    float* dst = (which == 0) ? g_q : (which == 1) ? g_k : g_v;

    #pragma unroll
    for (int u = 0; u < 8; u++) {
        const int m = m0 + ty * 8 + u;
        const int b = m >> 11;
        const int n = m & (N_ - 1);
        float* p = &dst[(((size_t)b * H_ + h) * N_ + n) * DH + d];
        *reinterpret_cast<float4*>(p)     = make_float4(acc[u][0], acc[u][1], acc[u][2], acc[u][3]);
        *reinterpret_cast<float4*>(p + 4) = make_float4(acc[u][4], acc[u][5], acc[u][6], acc[u][7]);
    }
}

// ---------------------------------------------------------------------------
// RoPE 2D applied in-place to g_q and g_k.
// ---------------------------------------------------------------------------
__global__ __launch_bounds__(256) void rope_kernel(const int* __restrict__ pos)
{
    const int t = blockIdx.x * blockDim.x + threadIdx.x;
    const int total = B_ * H_ * N_ * 32;
    if (t >= total) return;

    const int p = t & 31;
    const int row = t >> 5;           // (b*H + h)*N + n
    const int n = row & (N_ - 1);
    const int bh = row >> 11;
    const int b = bh >> 4;

    const int halfsel = p >> 4;
    const int i = p & 15;
    const int d1 = halfsel * 32 + i;
    const int d2 = d1 + 16;

    const float posv = (float)pos[((size_t)b * N_ + n) * 2 + halfsel];
    const float inv_freq = powf(100.0f, -(float)i / 16.0f);
    const float ang = posv * inv_freq;
    const float s = sinf(ang);
    const float c = cosf(ang);

    const size_t base = (size_t)row * DH;
    float q1 = g_q[base + d1], q2 = g_q[base + d2];
    g_q[base + d1] = q1 * c - q2 * s;
    g_q[base + d2] = q1 * s + q2 * c;
    float k1 = g_k[base + d1], k2 = g_k[base + d2];
    g_k[base + d1] = k1 * c - k2 * s;
    g_k[base + d2] = k1 * s + k2 * c;
}

// ---------------------------------------------------------------------------
// Flash attention: one CTA per (b, h, 128-row q tile). 256 threads.
// Microtile 8 rows x 4 cols. K tile = 64.
// Smem: Qs[d][i] stride 128, Ks[d][j] stride 64, Vs[j][d] stride 64,
//       Ps[i][j] stride 68.
// ---------------------------------------------------------------------------
#define PS_STR 68
#define SMEM_FLOATS (64*128 + 64*64 + 64*64 + 128*PS_STR)

__global__ __launch_bounds__(256, 2) void attn_kernel()
{
    extern __shared__ __align__(16) float sm[];
    float* Qs = sm;                     // [64][128] (d-major)
    float* Ks = sm + 64 * 128;          // [64][64]  (d-major)
    float* Vs = Ks + 64 * 64;           // [64][64]  (j-major)
    float* Ps = Vs + 64 * 64;           // [128][68]

    const int tid = threadIdx.x;
    const int tx = tid & 15;
    const int ty = tid >> 4;
    const int q0 = blockIdx.x * 128;
    const int h = blockIdx.y;
    const int b = blockIdx.z;

    const float* qptr = g_q + ((size_t)b * H_ + h) * N_ * DH;
    const float* kptr = g_k + ((size_t)b * H_ + h) * N_ * DH;
    const float* vptr = g_v + ((size_t)b * H_ + h) * N_ * DH;

    const float scale = 0.125f; // 64^-0.5

    // Load Q tile transposed: Qs[d][i], 128 rows x 16 float4 chunks
    for (int i4 = tid; i4 < 128 * 16; i4 += 256) {
        const int r = i4 >> 4;
        const int d4 = (i4 & 15) * 4;
        float4 qv = *reinterpret_cast<const float4*>(&qptr[(size_t)(q0 + r) * DH + d4]);
        Qs[(d4 + 0) * 128 + r] = qv.x;
        Qs[(d4 + 1) * 128 + r] = qv.y;
        Qs[(d4 + 2) * 128 + r] = qv.z;
        Qs[(d4 + 3) * 128 + r] = qv.w;
    }

    float m[8], l[8], acc[8][4];
    #pragma unroll
    for (int u = 0; u < 8; u++) {
        m[u] = -1e30f;
        l[u] = 0.f;
        #pragma unroll
        for (int v = 0; v < 4; v++) acc[u][v] = 0.f;
    }

    for (int kt = 0; kt < N_ / 64; kt++) {
        __syncthreads(); // protect Ks/Vs/Ps from previous iteration readers
        const int n0 = kt * 64;
        for (int i4 = tid; i4 < 64 * 16; i4 += 256) {
            const int r = i4 >> 4;
            const int d4 = (i4 & 15) * 4;
            float4 kv = *reinterpret_cast<const float4*>(&kptr[(size_t)(n0 + r) * DH + d4]);
            Ks[(d4 + 0) * 64 + r] = kv.x;
            Ks[(d4 + 1) * 64 + r] = kv.y;
            Ks[(d4 + 2) * 64 + r] = kv.z;
            Ks[(d4 + 3) * 64 + r] = kv.w;
            float4 vv = *reinterpret_cast<const float4*>(&vptr[(size_t)(n0 + r) * DH + d4]);
            *reinterpret_cast<float4*>(&Vs[r * 64 + d4]) = vv;
        }
        __syncthreads();

        // S = Q K^T : rows ty*8+u (8), cols tx*4+v (4)
        float s[8][4];
        #pragma unroll
        for (int u = 0; u < 8; u++)
            #pragma unroll
            for (int v = 0; v < 4; v++) s[u][v] = 0.f;

        #pragma unroll 8
        for (int d = 0; d < 64; d++) {
            float a[8];
            *reinterpret_cast<float4*>(&a[0]) = *reinterpret_cast<const float4*>(&Qs[d * 128 + ty * 8]);
            *reinterpret_cast<float4*>(&a[4]) = *reinterpret_cast<const float4*>(&Qs[d * 128 + ty * 8 + 4]);
            float4 bv = *reinterpret_cast<const float4*>(&Ks[d * 64 + tx * 4]);
            #pragma unroll
            for (int u = 0; u < 8; u++) {
                s[u][0] += a[u] * bv.x;
                s[u][1] += a[u] * bv.y;
                s[u][2] += a[u] * bv.z;
                s[u][3] += a[u] * bv.w;
            }
        }

        // Online softmax update per row
        #pragma unroll
        for (int u = 0; u < 8; u++) {
            float rmax = -1e30f;
            #pragma unroll
            for (int v = 0; v < 4; v++) {
                s[u][v] *= scale;
                rmax = fmaxf(rmax, s[u][v]);
            }
            #pragma unroll
            for (int off = 1; off < 16; off <<= 1)
                rmax = fmaxf(rmax, __shfl_xor_sync(0xffffffffu, rmax, off));

            const float newm = fmaxf(m[u], rmax);
            const float corr = __expf(m[u] - newm);
            float rsum = 0.f;
            #pragma unroll
            for (int v = 0; v < 4; v++) {
                s[u][v] = __expf(s[u][v] - newm);
                rsum += s[u][v];
            }
            #pragma unroll
            for (int off = 1; off < 16; off <<= 1)
                rsum += __shfl_xor_sync(0xffffffffu, rsum, off);

            l[u] = l[u] * corr + rsum;
            m[u] = newm;
            #pragma unroll
            for (int v = 0; v < 4; v++) acc[u][v] *= corr;
            *reinterpret_cast<float4*>(&Ps[(ty * 8 + u) * PS_STR + tx * 4]) =
                make_float4(s[u][0], s[u][1], s[u][2], s[u][3]);
        }
        __syncthreads();

        // O += P @ V : blocked j by 4, P loads are float4 broadcasts
        #pragma unroll 2
        for (int j = 0; j < 64; j += 4) {
            float4 v0 = *reinterpret_cast<const float4*>(&Vs[(j + 0) * 64 + tx * 4]);
            float4 v1 = *reinterpret_cast<const float4*>(&Vs[(j + 1) * 64 + tx * 4]);
            float4 v2 = *reinterpret_cast<const float4*>(&Vs[(j + 2) * 64 + tx * 4]);
            float4 v3 = *reinterpret_cast<const float4*>(&Vs[(j + 3) * 64 + tx * 4]);
            #pragma unroll
            for (int u = 0; u < 8; u++) {
                float4 p4 = *reinterpret_cast<const float4*>(&Ps[(ty * 8 + u) * PS_STR + j]);
                acc[u][0] += p4.x * v0.x; acc[u][1] += p4.x * v0.y; acc[u][2] += p4.x * v0.z; acc[u][3] += p4.x * v0.w;
                acc[u][0] += p4.y * v1.x; acc[u][1] += p4.y * v1.y; acc[u][2] += p4.y * v1.z; acc[u][3] += p4.y * v1.w;
                acc[u][0] += p4.z * v2.x; acc[u][1] += p4.z * v2.y; acc[u][2] += p4.z * v2.z; acc[u][3] += p4.z * v2.w;
                acc[u][0] += p4.w * v3.x; acc[u][1] += p4.w * v3.y; acc[u][2] += p4.w * v3.z; acc[u][3] += p4.w * v3.w;
            }
        }
    }

    // Write normalized output to g_att in [B, N, H*DH] layout
    #pragma unroll
    for (int u = 0; u < 8; u++) {
        const float inv_l = 1.0f / l[u];
        const int n = q0 + ty * 8 + u;
        float4 o = make_float4(acc[u][0] * inv_l, acc[u][1] * inv_l,
                               acc[u][2] * inv_l, acc[u][3] * inv_l);
        *reinterpret_cast<float4*>(&g_att[((size_t)b * N_ + n) * C_ + h * DH + tx * 4]) = o;
    }
}

// ---------------------------------------------------------------------------
// Output projection: out[m][j] = sum_k g_att[m][k] * proj_w[j][k] + proj_b[j]
// M=4096, N=1024, K=1024. Tile 128x128x16, 8x8 microtile.
// ---------------------------------------------------------------------------
__global__ __launch_bounds__(256, 2) void proj_gemm_kernel(
    const float* __restrict__ w, const float* __restrict__ bias,
    float* __restrict__ out)
{
    __shared__ __align__(16) float As[16][128];
    __shared__ __align__(16) float Ws[16][128];

    const int tid = threadIdx.x;
    const int tx = tid & 15;
    const int ty = tid >> 4;
    const int m0 = blockIdx.y * 128;
    const int j0 = blockIdx.x * 128;

    const int lr = tid >> 1;
    const int lk = (tid & 1) * 8;

    float acc[8][8];
    #pragma unroll
    for (int u = 0; u < 8; u++)
        #pragma unroll
        for (int v = 0; v < 8; v++) acc[u][v] = 0.f;

    for (int k0 = 0; k0 < C_; k0 += 16) {
        float4 a0 = *reinterpret_cast<const float4*>(&g_att[(size_t)(m0 + lr) * C_ + k0 + lk]);
        float4 a1 = *reinterpret_cast<const float4*>(&g_att[(size_t)(m0 + lr) * C_ + k0 + lk + 4]);
        float4 b0 = *reinterpret_cast<const float4*>(&w[(size_t)(j0 + lr) * C_ + k0 + lk]);
        float4 b1 = *reinterpret_cast<const float4*>(&w[(size_t)(j0 + lr) * C_ + k0 + lk + 4]);
        As[lk + 0][lr] = a0.x; As[lk + 1][lr] = a0.y; As[lk + 2][lr] = a0.z; As[lk + 3][lr] = a0.w;
        As[lk + 4][lr] = a1.x; As[lk + 5][lr] = a1.y; As[lk + 6][lr] = a1.z; As[lk + 7][lr] = a1.w;
        Ws[lk + 0][lr] = b0.x; Ws[lk + 1][lr] = b0.y; Ws[lk + 2][lr] = b0.z; Ws[lk + 3][lr] = b0.w;
        Ws[lk + 4][lr] = b1.x; Ws[lk + 5][lr] = b1.y; Ws[lk + 6][lr] = b1.z; Ws[lk + 7][lr] = b1.w;
        __syncthreads();

        #pragma unroll
        for (int k = 0; k < 16; k++) {
            float a[8], b[8];
            *reinterpret_cast<float4*>(&a[0]) = *reinterpret_cast<const float4*>(&As[k][ty * 8]);
            *reinterpret_cast<float4*>(&a[4]) = *reinterpret_cast<const float4*>(&As[k][ty * 8 + 4]);
            *reinterpret_cast<float4*>(&b[0]) = *reinterpret_cast<const float4*>(&Ws[k][tx * 8]);
            *reinterpret_cast<float4*>(&b[4]) = *reinterpret_cast<const float4*>(&Ws[k][tx * 8 + 4]);
            #pragma unroll
            for (int u = 0; u < 8; u++)
                #pragma unroll
                for (int v = 0; v < 8; v++)
                    acc[u][v] += a[u] * b[v];
        }
        __syncthreads();
    }

    const int j = j0 + tx * 8;
    float4 bv0 = *reinterpret_cast<const float4*>(&bias[j]);
    float4 bv1 = *reinterpret_cast<const float4*>(&bias[j + 4]);
    #pragma unroll
    for (int u = 0; u < 8; u++) {
        const int mm = m0 + ty * 8 + u;
        float* p = &out[(size_t)mm * C_ + j];
        *reinterpret_cast<float4*>(p) = make_float4(acc[u][0] + bv0.x, acc[u][1] + bv0.y,
                                                    acc[u][2] + bv0.z, acc[u][3] + bv0.w);
        *reinterpret_cast<float4*>(p + 4) = make_float4(acc[u][4] + bv1.x, acc[u][5] + bv1.y,
                                                        acc[u][6] + bv1.z, acc[u][7] + bv1.w);
    }
}

// ---------------------------------------------------------------------------
extern "C" void kernel_launch(void* const* d_in, const int* in_sizes, int n_in,
                              void* d_out, int out_size)
{
    const float* x      = (const float*)d_in[0];
    const int*   pos    = (const int*)  d_in[1];
    const float* qkv_w  = (const float*)d_in[2];
    const float* proj_w = (const float*)d_in[3];
    const float* proj_b = (const float*)d_in[4];
    float* out = (float*)d_out;

    const int attn_smem = SMEM_FLOATS * (int)sizeof(float); // 100352 B
    cudaFuncSetAttribute(attn_kernel,
                         cudaFuncAttributeMaxDynamicSharedMemorySize, attn_smem);

    // 1) QKV projection + scatter to [B,H,N,DH]
    {
        dim3 grid(3 * C_ / 128, (B_ * N_) / 128); // (24, 32)
        qkv_gemm_kernel<<<grid, 256>>>(x, qkv_w);
    }
    // 2) RoPE on q and k
    {
        const int total = B_ * H_ * N_ * 32;
        rope_kernel<<<(total + 255) / 256, 256>>>(pos);
    }
    // 3) Attention
    {
        dim3 grid(N_ / 128, H_, B_); // (16, 16, 2)
        attn_kernel<<<grid, 256, attn_smem>>>();
    }
    // 4) Output projection + bias
    {
        dim3 grid(C_ / 128, (B_ * N_) / 128); // (8, 32)
        proj_gemm_kernel<<<grid, 256>>>(proj_w, proj_b, out);
    }
}

// round 3
// speedup vs baseline: 3.1680x; 2.6671x over previous
#include <cuda_runtime.h>
#include <cuda_bf16.h>
#include <math.h>
#include <stdint.h>

#define B_  2
#define N_  2048
#define C_  1024
#define H_  16
#define DH  64

// Scratch (device globals: allocation-free per harness rules)
__device__ float g_q[B_*H_*N_*DH];
__device__ float g_k[B_*H_*N_*DH];
__device__ float g_v[B_*H_*N_*DH];
__device__ float g_att[B_*N_*C_];

__device__ __forceinline__ uint32_t f2tf(float f) {
    uint32_t u;
    asm("cvt.rna.tf32.f32 %0, %1;" : "=r"(u) : "f"(f));
    return u;
}

__device__ __forceinline__ void mma_tf32(float c[4], uint32_t a0, uint32_t a1,
                                         uint32_t a2, uint32_t a3,
                                         uint32_t b0, uint32_t b1) {
    asm volatile(
        "mma.sync.aligned.m16n8k8.row.col.f32.tf32.tf32.f32 "
        "{%0,%1,%2,%3}, {%4,%5,%6,%7}, {%8,%9}, {%0,%1,%2,%3};"
        : "+f"(c[0]), "+f"(c[1]), "+f"(c[2]), "+f"(c[3])
        : "r"(a0), "r"(a1), "r"(a2), "r"(a3), "r"(b0), "r"(b1));
}

// ---------------------------------------------------------------------------
// QKV GEMM (tf32 mma): out[m][j] = sum_k x[m][k] * qkv_w[j][k]
// M=4096, N=3072, K=1024. CTA tile 128x128x32. 8 warps (2m x 4n), 64x32/warp.
// Smem [row][36] padding -> conflict-free fragment LDS.
// Epilogue scatters into g_q/g_k/g_v in [B,H,N,DH] layout.
// ---------------------------------------------------------------------------
__global__ __launch_bounds__(256, 2) void qkv_gemm_kernel(
    const float* __restrict__ x, const float* __restrict__ w)
{
    __shared__ uint32_t As[128 * 36];
    __shared__ uint32_t Ws[128 * 36];

    const int tid = threadIdx.x;
    const int lane = tid & 31;
    const int wid = tid >> 5;
    const int wm = wid >> 2;        // 0..1
    const int wn = wid & 3;         // 0..3
    const int g = lane >> 2;        // 0..7
    const int t = lane & 3;         // 0..3

    const int m0 = blockIdx.y * 128;
    const int j0 = blockIdx.x * 128;

    const int sr = tid >> 1;        // staging row 0..127
    const int sc = (tid & 1) * 16;  // staging col 0 or 16

    float c[4][4][4];
    #pragma unroll
    for (int mf = 0; mf < 4; mf++)
        #pragma unroll
        for (int nf = 0; nf < 4; nf++)
            #pragma unroll
            for (int i = 0; i < 4; i++) c[mf][nf][i] = 0.f;

    for (int k0 = 0; k0 < C_; k0 += 32) {
        __syncthreads();
        const float* srcA = &x[(size_t)(m0 + sr) * C_ + k0 + sc];
        const float* srcB = &w[(size_t)(j0 + sr) * C_ + k0 + sc];
        #pragma unroll
        for (int i = 0; i < 4; i++) {
            float4 va = *reinterpret_cast<const float4*>(srcA + i * 4);
            float4 vb = *reinterpret_cast<const float4*>(srcB + i * 4);
            uint4 ua = make_uint4(f2tf(va.x), f2tf(va.y), f2tf(va.z), f2tf(va.w));
            uint4 ub = make_uint4(f2tf(vb.x), f2tf(vb.y), f2tf(vb.z), f2tf(vb.w));
            *reinterpret_cast<uint4*>(&As[sr * 36 + sc + i * 4]) = ua;
            *reinterpret_cast<uint4*>(&Ws[sr * 36 + sc + i * 4]) = ub;
        }
        __syncthreads();

        #pragma unroll
        for (int kk = 0; kk < 4; kk++) {
            const int k8 = kk * 8;
            uint32_t a[4][4];
            #pragma unroll
            for (int mf = 0; mf < 4; mf++) {
                const int r0 = wm * 64 + mf * 16 + g;
                a[mf][0] = As[r0 * 36 + k8 + t];
                a[mf][1] = As[(r0 + 8) * 36 + k8 + t];
                a[mf][2] = As[r0 * 36 + k8 + t + 4];
                a[mf][3] = As[(r0 + 8) * 36 + k8 + t + 4];
            }
            #pragma unroll
            for (int nf = 0; nf < 4; nf++) {
                const int jr = wn * 32 + nf * 8 + g;
                uint32_t b0 = Ws[jr * 36 + k8 + t];
                uint32_t b1 = Ws[jr * 36 + k8 + t + 4];
                #pragma unroll
                for (int mf = 0; mf < 4; mf++)
                    mma_tf32(c[mf][nf], a[mf][0], a[mf][1], a[mf][2], a[mf][3], b0, b1);
            }
        }
    }

    // Epilogue: scatter. col j = j0 + wn*32 + nf*8 + 2t (+1); row m0 + wm*64 + mf*16 + g (+8)
    #pragma unroll
    for (int nf = 0; nf < 4; nf++) {
        const int j = j0 + wn * 32 + nf * 8 + 2 * t;
        const int which = j >> 10;
        const int h = (j >> 6) & (H_ - 1);
        const int d = j & (DH - 1);
        float* dst = (which == 0) ? g_q : (which == 1) ? g_k : g_v;
        #pragma unroll
        for (int mf = 0; mf < 4; mf++) {
            const int m = m0 + wm * 64 + mf * 16 + g;
            const int b = m >> 11;
            const int n = m & (N_ - 1);
            float* p0 = &dst[(((size_t)b * H_ + h) * N_ + n) * DH + d];
            *reinterpret_cast<float2*>(p0) = make_float2(c[mf][nf][0], c[mf][nf][1]);
            const int m2 = m + 8;
            const int b2 = m2 >> 11;
            const int n2 = m2 & (N_ - 1);
            float* p1 = &dst[(((size_t)b2 * H_ + h) * N_ + n2) * DH + d];
            *reinterpret_cast<float2*>(p1) = make_float2(c[mf][nf][2], c[mf][nf][3]);
        }
    }
}

// ---------------------------------------------------------------------------
// RoPE 2D applied in-place to g_q and g_k.
// ---------------------------------------------------------------------------
__global__ __launch_bounds__(256) void rope_kernel(const int* __restrict__ pos)
{
    const int tt = blockIdx.x * blockDim.x + threadIdx.x;
    const int total = B_ * H_ * N_ * 32;
    if (tt >= total) return;

    const int p = tt & 31;
    const int row = tt >> 5;          // (b*H + h)*N + n
    const int n = row & (N_ - 1);
    const int bh = row >> 11;
    const int b = bh >> 4;

    const int halfsel = p >> 4;
    const int i = p & 15;
    const int d1 = halfsel * 32 + i;
    const int d2 = d1 + 16;

    const float posv = (float)pos[((size_t)b * N_ + n) * 2 + halfsel];
    const float inv_freq = powf(100.0f, -(float)i / 16.0f);
    const float ang = posv * inv_freq;
    const float s = sinf(ang);
    const float c = cosf(ang);

    const size_t base = (size_t)row * DH;
    float q1 = g_q[base + d1], q2 = g_q[base + d2];
    g_q[base + d1] = q1 * c - q2 * s;
    g_q[base + d2] = q1 * s + q2 * c;
    float k1 = g_k[base + d1], k2 = g_k[base + d2];
    g_k[base + d1] = k1 * c - k2 * s;
    g_k[base + d2] = k1 * s + k2 * c;
}

// ---------------------------------------------------------------------------
// Flash attention (tf32 mma): CTA = (b, h, 128-query tile), 256 thr = 8 warps.
// Warp w owns query rows w*16..w*16+15. Key tile = 64.
// Smem (uint32 tf32): Qs[128][68], Ks[64][68], Vs[64][72], Ps[128][68].
// ---------------------------------------------------------------------------
#define ATTN_SMEM_WORDS (128*68 + 64*68 + 64*72 + 128*68)

__global__ __launch_bounds__(256, 2) void attn_kernel()
{
    extern __shared__ uint32_t smw[];
    uint32_t* Qs = smw;                       // [128][68]
    uint32_t* Ks = Qs + 128 * 68;             // [64][68]
    uint32_t* Vs = Ks + 64 * 68;              // [64][72]
    uint32_t* Ps = Vs + 64 * 72;              // [128][68]

    const int tid = threadIdx.x;
    const int lane = tid & 31;
    const int wid = tid >> 5;
    const int g = lane >> 2;
    const int t = lane & 3;
    const int rb = wid * 16;                  // warp's query row base (local)

    const int q0 = blockIdx.x * 128;
    const int h = blockIdx.y;
    const int b = blockIdx.z;

    const float* qptr = g_q + ((size_t)b * H_ + h) * N_ * DH;
    const float* kptr = g_k + ((size_t)b * H_ + h) * N_ * DH;
    const float* vptr = g_v + ((size_t)b * H_ + h) * N_ * DH;

    // Stage Q (scale 0.125 folded in, tf32)
    for (int idx = tid; idx < 128 * 16; idx += 256) {
        const int r = idx >> 4;
        const int c4 = (idx & 15) * 4;
        float4 v = *reinterpret_cast<const float4*>(&qptr[(size_t)(q0 + r) * DH + c4]);
        uint4 u = make_uint4(f2tf(v.x * 0.125f), f2tf(v.y * 0.125f),
                             f2tf(v.z * 0.125f), f2tf(v.w * 0.125f));
        *reinterpret_cast<uint4*>(&Qs[r * 68 + c4]) = u;
    }

    float o[8][4];
    #pragma unroll
    for (int df = 0; df < 8; df++)
        #pragma unroll
        for (int i = 0; i < 4; i++) o[df][i] = 0.f;
    float mrow0 = -1e30f, mrow1 = -1e30f, lrow0 = 0.f, lrow1 = 0.f;

    for (int kt = 0; kt < N_ / 64; kt++) {
        __syncthreads();   // previous tile's Ks/Vs consumers done (also covers Q staging)
        const int n0 = kt * 64;
        for (int idx = tid; idx < 64 * 16; idx += 256) {
            const int r = idx >> 4;
            const int c4 = (idx & 15) * 4;
            float4 kv = *reinterpret_cast<const float4*>(&kptr[(size_t)(n0 + r) * DH + c4]);
            *reinterpret_cast<uint4*>(&Ks[r * 68 + c4]) =
                make_uint4(f2tf(kv.x), f2tf(kv.y), f2tf(kv.z), f2tf(kv.w));
            float4 vv = *reinterpret_cast<const float4*>(&vptr[(size_t)(n0 + r) * DH + c4]);
            *reinterpret_cast<uint4*>(&Vs[r * 72 + c4]) =
                make_uint4(f2tf(vv.x), f2tf(vv.y), f2tf(vv.z), f2tf(vv.w));
        }
        __syncthreads();

        // S = Q K^T for this warp's 16 rows x 64 keys
        float s[8][4];
        #pragma unroll
        for (int nf = 0; nf < 8; nf++)
            #pragma unroll
            for (int i = 0; i < 4; i++) s[nf][i] = 0.f;

        #pragma unroll
        for (int k8 = 0; k8 < 64; k8 += 8) {
            uint32_t a0 = Qs[(rb + g) * 68 + k8 + t];
            uint32_t a1 = Qs[(rb + g + 8) * 68 + k8 + t];
            uint32_t a2 = Qs[(rb + g) * 68 + k8 + t + 4];
            uint32_t a3 = Qs[(rb + g + 8) * 68 + k8 + t + 4];
            #pragma unroll
            for (int nf = 0; nf < 8; nf++) {
                uint32_t b0 = Ks[(nf * 8 + g) * 68 + k8 + t];
                uint32_t b1 = Ks[(nf * 8 + g) * 68 + k8 + t + 4];
                mma_tf32(s[nf], a0, a1, a2, a3, b0, b1);
            }
        }

        // Online softmax. Row g -> (c0,c1), row g+8 -> (c2,c3).
        float rmax0 = -1e30f, rmax1 = -1e30f;
        #pragma unroll
        for (int nf = 0; nf < 8; nf++) {
            rmax0 = fmaxf(rmax0, fmaxf(s[nf][0], s[nf][1]));
            rmax1 = fmaxf(rmax1, fmaxf(s[nf][2], s[nf][3]));
        }
        #pragma unroll
        for (int off = 1; off < 4; off <<= 1) {
            rmax0 = fmaxf(rmax0, __shfl_xor_sync(0xffffffffu, rmax0, off));
            rmax1 = fmaxf(rmax1, __shfl_xor_sync(0xffffffffu, rmax1, off));
        }
        const float newm0 = fmaxf(mrow0, rmax0);
        const float newm1 = fmaxf(mrow1, rmax1);
        const float corr0 = __expf(mrow0 - newm0);
        const float corr1 = __expf(mrow1 - newm1);

        float rsum0 = 0.f, rsum1 = 0.f;
        #pragma unroll
        for (int nf = 0; nf < 8; nf++) {
            float p0 = __expf(s[nf][0] - newm0);
            float p1 = __expf(s[nf][1] - newm0);
            float p2 = __expf(s[nf][2] - newm1);
            float p3 = __expf(s[nf][3] - newm1);
            rsum0 += p0 + p1;
            rsum1 += p2 + p3;
            *reinterpret_cast<uint2*>(&Ps[(rb + g) * 68 + nf * 8 + 2 * t]) =
                make_uint2(f2tf(p0), f2tf(p1));
            *reinterpret_cast<uint2*>(&Ps[(rb + g + 8) * 68 + nf * 8 + 2 * t]) =
                make_uint2(f2tf(p2), f2tf(p3));
        }
        #pragma unroll
        for (int off = 1; off < 4; off <<= 1) {
            rsum0 += __shfl_xor_sync(0xffffffffu, rsum0, off);
            rsum1 += __shfl_xor_sync(0xffffffffu, rsum1, off);
        }
        lrow0 = lrow0 * corr0 + rsum0;
        lrow1 = lrow1 * corr1 + rsum1;
        mrow0 = newm0;
        mrow1 = newm1;
        #pragma unroll
        for (int df = 0; df < 8; df++) {
            o[df][0] *= corr0; o[df][1] *= corr0;
            o[df][2] *= corr1; o[df][3] *= corr1;
        }
        __syncwarp();

        // O += P V  (P warp-private rows in smem)
        #pragma unroll
        for (int k8 = 0; k8 < 64; k8 += 8) {
            uint32_t a0 = Ps[(rb + g) * 68 + k8 + t];
            uint32_t a1 = Ps[(rb + g + 8) * 68 + k8 + t];
            uint32_t a2 = Ps[(rb + g) * 68 + k8 + t + 4];
            uint32_t a3 = Ps[(rb + g + 8) * 68 + k8 + t + 4];
            #pragma unroll
            for (int df = 0; df < 8; df++) {
                uint32_t b0 = Vs[(k8 + t) * 72 + df * 8 + g];
                uint32_t b1 = Vs[(k8 + t + 4) * 72 + df * 8 + g];
                mma_tf32(o[df], a0, a1, a2, a3, b0, b1);
            }
        }
        __syncwarp();   // warp done reading Ps before next iteration overwrites
    }

    // Normalize + store to g_att [B, N, H*DH]
    const float inv0 = 1.0f / lrow0;
    const float inv1 = 1.0f / lrow1;
    const int n0 = q0 + rb + g;
    const int n1 = n0 + 8;
    #pragma unroll
    for (int df = 0; df < 8; df++) {
        const int d = df * 8 + 2 * t;
        *reinterpret_cast<float2*>(&g_att[((size_t)b * N_ + n0) * C_ + h * DH + d]) =
            make_float2(o[df][0] * inv0, o[df][1] * inv0);
        *reinterpret_cast<float2*>(&g_att[((size_t)b * N_ + n1) * C_ + h * DH + d]) =
            make_float2(o[df][2] * inv1, o[df][3] * inv1);
    }
}

// ---------------------------------------------------------------------------
// Output projection (tf32 mma): out[m][j] = sum_k g_att[m][k]*proj_w[j][k] + b[j]
// M=4096, N=1024, K=1024. Same structure as qkv_gemm.
// ---------------------------------------------------------------------------
__global__ __launch_bounds__(256, 2) void proj_gemm_kernel(
    const float* __restrict__ w, const float* __restrict__ bias,
    float* __restrict__ out)
{
    __shared__ uint32_t As[128 * 36];
    __shared__ uint32_t Ws[128 * 36];

    const int tid = threadIdx.x;
    const int lane = tid & 31;
    const int wid = tid >> 5;
    const int wm = wid >> 2;
    const int wn = wid & 3;
    const int g = lane >> 2;
    const int t = lane & 3;

    const int m0 = blockIdx.y * 128;
    const int j0 = blockIdx.x * 128;

    const int sr = tid >> 1;
    const int sc = (tid & 1) * 16;

    float c[4][4][4];
    #pragma unroll
    for (int mf = 0; mf < 4; mf++)
        #pragma unroll
        for (int nf = 0; nf < 4; nf++)
            #pragma unroll
            for (int i = 0; i < 4; i++) c[mf][nf][i] = 0.f;

    for (int k0 = 0; k0 < C_; k0 += 32) {
        __syncthreads();
        const float* srcA = &g_att[(size_t)(m0 + sr) * C_ + k0 + sc];
        const float* srcB = &w[(size_t)(j0 + sr) * C_ + k0 + sc];
        #pragma unroll
        for (int i = 0; i < 4; i++) {
            float4 va = *reinterpret_cast<const float4*>(srcA + i * 4);
            float4 vb = *reinterpret_cast<const float4*>(srcB + i * 4);
            *reinterpret_cast<uint4*>(&As[sr * 36 + sc + i * 4]) =
                make_uint4(f2tf(va.x), f2tf(va.y), f2tf(va.z), f2tf(va.w));
            *reinterpret_cast<uint4*>(&Ws[sr * 36 + sc + i * 4]) =
                make_uint4(f2tf(vb.x), f2tf(vb.y), f2tf(vb.z), f2tf(vb.w));
        }
        __syncthreads();

        #pragma unroll
        for (int kk = 0; kk < 4; kk++) {
            const int k8 = kk * 8;
            uint32_t a[4][4];
            #pragma unroll
            for (int mf = 0; mf < 4; mf++) {
                const int r0 = wm * 64 + mf * 16 + g;
                a[mf][0] = As[r0 * 36 + k8 + t];
                a[mf][1] = As[(r0 + 8) * 36 + k8 + t];
                a[mf][2] = As[r0 * 36 + k8 + t + 4];
                a[mf][3] = As[(r0 + 8) * 36 + k8 + t + 4];
            }
            #pragma unroll
            for (int nf = 0; nf < 4; nf++) {
                const int jr = wn * 32 + nf * 8 + g;
                uint32_t b0 = Ws[jr * 36 + k8 + t];
                uint32_t b1 = Ws[jr * 36 + k8 + t + 4];
                #pragma unroll
                for (int mf = 0; mf < 4; mf++)
                    mma_tf32(c[mf][nf], a[mf][0], a[mf][1], a[mf][2], a[mf][3], b0, b1);
            }
        }
    }

    #pragma unroll
    for (int nf = 0; nf < 4; nf++) {
        const int j = j0 + wn * 32 + nf * 8 + 2 * t;
        const float b0v = bias[j];
        const float b1v = bias[j + 1];
        #pragma unroll
        for (int mf = 0; mf < 4; mf++) {
            const int m = m0 + wm * 64 + mf * 16 + g;
            *reinterpret_cast<float2*>(&out[(size_t)m * C_ + j]) =
                make_float2(c[mf][nf][0] + b0v, c[mf][nf][1] + b1v);
            *reinterpret_cast<float2*>(&out[(size_t)(m + 8) * C_ + j]) =
                make_float2(c[mf][nf][2] + b0v, c[mf][nf][3] + b1v);
        }
    }
}

// ---------------------------------------------------------------------------
extern "C" void kernel_launch(void* const* d_in, const int* in_sizes, int n_in,
                              void* d_out, int out_size)
{
    const float* x      = (const float*)d_in[0];
    const int*   pos    = (const int*)  d_in[1];
    const float* qkv_w  = (const float*)d_in[2];
    const float* proj_w = (const float*)d_in[3];
    const float* proj_b = (const float*)d_in[4];
    float* out = (float*)d_out;

    const int attn_smem = ATTN_SMEM_WORDS * 4; // 105472 B
    cudaFuncSetAttribute(attn_kernel,
                         cudaFuncAttributeMaxDynamicSharedMemorySize, attn_smem);

    // 1) QKV projection + scatter to [B,H,N,DH]
    {
        dim3 grid(3 * C_ / 128, (B_ * N_) / 128); // (24, 32)
        qkv_gemm_kernel<<<grid, 256>>>(x, qkv_w);
    }
    // 2) RoPE on q and k
    {
        const int total = B_ * H_ * N_ * 32;
        rope_kernel<<<(total + 255) / 256, 256>>>(pos);
    }
    // 3) Attention
    {
        dim3 grid(N_ / 128, H_, B_); // (16, 16, 2)
        attn_kernel<<<grid, 256, attn_smem>>>();
    }
    // 4) Output projection + bias
    {
        dim3 grid(C_ / 128, (B_ * N_) / 128); // (8, 32)
        proj_gemm_kernel<<<grid, 256>>>(proj_w, proj_b, out);
    }
}